// round 8
// baseline (speedup 1.0000x reference)
#include <cuda_runtime.h>
#include <cuda_fp16.h>
#include <cstdint>

#define NND 100000
#define NED 3200000
#define IN_DIM 128
#define HID 64
#define NCLS 8
#define NBLK 391   // ceil(NND/256)

// ---------------- device scratch ----------------
__device__ __half2 g_hproj[(size_t)NND * 32];  // N x 64 halves = 12.8 MB
__device__ __half2 g_h2[(size_t)NND * 4];      // N x 8 halves  = 1.6 MB
__device__ float g_onorm[NND];
__device__ float g_innorm[NND];
__device__ int   g_outdeg[NND];
__device__ int   g_indeg[NND];
__device__ int   g_csr_src[NED + 64];          // +64 pad for unguarded prefetch
__device__ int   g_start[NND];
__device__ int   g_cursor[NND];
__device__ int   g_total;

// ---------------- mma helpers ----------------
__device__ __forceinline__ uint32_t smem_u32(const void* p) {
    return (uint32_t)__cvta_generic_to_shared(p);
}
__device__ __forceinline__ void ldsm_x4(uint32_t addr, uint32_t& r0, uint32_t& r1,
                                        uint32_t& r2, uint32_t& r3) {
    asm volatile("ldmatrix.sync.aligned.m8n8.x4.shared.b16 {%0,%1,%2,%3}, [%4];"
                 : "=r"(r0), "=r"(r1), "=r"(r2), "=r"(r3) : "r"(addr));
}
__device__ __forceinline__ void ldsm_x4_t(uint32_t addr, uint32_t& r0, uint32_t& r1,
                                          uint32_t& r2, uint32_t& r3) {
    asm volatile("ldmatrix.sync.aligned.m8n8.x4.trans.shared.b16 {%0,%1,%2,%3}, [%4];"
                 : "=r"(r0), "=r"(r1), "=r"(r2), "=r"(r3) : "r"(addr));
}
__device__ __forceinline__ void mma_16816(float (&c)[4], uint32_t a0, uint32_t a1,
                                          uint32_t a2, uint32_t a3,
                                          uint32_t b0, uint32_t b1) {
    asm volatile("mma.sync.aligned.m16n8k16.row.col.f32.f16.f16.f32 "
                 "{%0,%1,%2,%3}, {%4,%5,%6,%7}, {%8,%9}, {%0,%1,%2,%3};"
                 : "+f"(c[0]), "+f"(c[1]), "+f"(c[2]), "+f"(c[3])
                 : "r"(a0), "r"(a1), "r"(a2), "r"(a3), "r"(b0), "r"(b1));
}

// ---------------- launch 1: zero ----------------
__global__ void k_zero() {
    int i = blockIdx.x * 256 + threadIdx.x;
    if (i < NND) { g_outdeg[i] = 0; g_indeg[i] = 0; }
    if (i < 64)  g_csr_src[NED + i] = 0;
    if (i == 0)  g_total = 0;
}

// ---------------- launch 2: degrees ----------------
__global__ void k_degree(const int* __restrict__ src, const int* __restrict__ dst) {
    int e = blockIdx.x * 256 + threadIdx.x;   // exact grid
    atomicAdd(&g_outdeg[__ldg(src + e)], 1);
    atomicAdd(&g_indeg[__ldg(dst + e)], 1);
}

// ---------------- launch 3: norms + CSR start offsets ----------------
__global__ void __launch_bounds__(256) k_norm_start() {
    int t = threadIdx.x;
    int n = blockIdx.x * 256 + t;
    int lane = t & 31, w = t >> 5;

    int deg = 0, od = 0;
    if (n < NND) { deg = g_indeg[n]; od = g_outdeg[n]; }

    int scan = deg;
    #pragma unroll
    for (int off = 1; off < 32; off <<= 1) {
        int u = __shfl_up_sync(~0u, scan, off);
        if (lane >= off) scan += u;
    }
    __shared__ int wsum[8];
    __shared__ int sbase;
    if (lane == 31) wsum[w] = scan;
    __syncthreads();
    if (t == 0) {
        int tot = 0;
        #pragma unroll
        for (int i = 0; i < 8; i++) { int v = wsum[i]; wsum[i] = tot; tot += v; }
        sbase = atomicAdd(&g_total, tot);
    }
    __syncthreads();

    if (n < NND) {
        g_onorm[n]  = rsqrtf((float)(od  > 1 ? od  : 1));
        g_innorm[n] = rsqrtf((float)(deg > 1 ? deg : 1));
        int start = sbase + wsum[w] + scan - deg;
        g_start[n]  = start;
        g_cursor[n] = start;
    }
}

// ---------------- launch 4 (PROFILED): GEMM1 via fp16 mma.sync ----------------
#define XS_STR 72
#define WS_STR 72

__global__ void __launch_bounds__(256) k_gemm1(const float* __restrict__ x,
                                               const float* __restrict__ W1) {
    __shared__ __half xs[128 * XS_STR];
    __shared__ __half ws[64 * WS_STR];
    __shared__ float  ns[128];

    int t = threadIdx.x;
    int w = t >> 5, lane = t & 31;
    int nb = blockIdx.x * 128;

    if (t < 128) ns[t] = (nb + t < NND) ? g_onorm[nb + t] : 0.0f;
    __syncthreads();

    float acc[8][4] = {};

    uint32_t xbase = smem_u32(xs);
    uint32_t wbase = smem_u32(ws);
    int arow  = (w << 4) + (lane & 15);
    int ahalf = lane >> 4;
    int brow  = lane & 15;
    int bsel  = lane >> 4;

    for (int kc = 0; kc < 2; kc++) {
        #pragma unroll
        for (int i = 0; i < 8; i++) {
            int li  = i * 256 + t;
            int row = li >> 4;
            int f4  = li & 15;
            int gn  = nb + row;
            float4 v = (gn < NND)
                ? __ldg((const float4*)(x + (size_t)gn * IN_DIM + kc * 64) + f4)
                : make_float4(0.f, 0.f, 0.f, 0.f);
            float nrm = ns[row];
            __half2 h[2];
            h[0] = __floats2half2_rn(v.x * nrm, v.y * nrm);
            h[1] = __floats2half2_rn(v.z * nrm, v.w * nrm);
            *(uint2*)(xs + row * XS_STR + f4 * 4) = *(uint2*)h;
        }
        #pragma unroll
        for (int i = 0; i < 4; i++) {
            int li = i * 256 + t;
            int kr = li >> 4;
            int f4 = li & 15;
            float4 v = __ldg((const float4*)(W1 + (size_t)(kc * 64 + kr) * HID) + f4);
            __half2 h[2];
            h[0] = __floats2half2_rn(v.x, v.y);
            h[1] = __floats2half2_rn(v.z, v.w);
            *(uint2*)(ws + kr * WS_STR + f4 * 4) = *(uint2*)h;
        }
        __syncthreads();

        #pragma unroll
        for (int ks = 0; ks < 4; ks++) {
            uint32_t a0, a1, a2, a3;
            ldsm_x4(xbase + (uint32_t)(arow * (XS_STR * 2) + ks * 32 + ahalf * 16),
                    a0, a1, a2, a3);
            #pragma unroll
            for (int np = 0; np < 4; np++) {
                uint32_t b0, b1, b2, b3;
                uint32_t baddr = wbase
                    + (uint32_t)((ks * 16 + brow) * (WS_STR * 2))
                    + (uint32_t)((np * 2 + bsel) * 16);
                ldsm_x4_t(baddr, b0, b1, b2, b3);
                mma_16816(acc[2 * np],     a0, a1, a2, a3, b0, b1);
                mma_16816(acc[2 * np + 1], a0, a1, a2, a3, b2, b3);
            }
        }
        __syncthreads();
    }

    int g  = lane >> 2, tg = lane & 3;
    int m0 = nb + (w << 4) + g;
    int m1 = m0 + 8;
    #pragma unroll
    for (int nt = 0; nt < 8; nt++) {
        if (m0 < NND)
            g_hproj[(size_t)m0 * 32 + nt * 4 + tg] = __floats2half2_rn(acc[nt][0], acc[nt][1]);
        if (m1 < NND)
            g_hproj[(size_t)m1 * 32 + nt * 4 + tg] = __floats2half2_rn(acc[nt][2], acc[nt][3]);
    }
}

// ---------------- launch 5: CSR fill ----------------
__global__ void k_fill(const int* __restrict__ src, const int* __restrict__ dst) {
    int e = blockIdx.x * 256 + threadIdx.x;   // exact grid
    int d = __ldg(dst + e);
    int s = __ldg(src + e);
    int pos = atomicAdd(&g_cursor[d], 1);
    g_csr_src[pos] = s;
}

// ---------------- launch 6: fused aggregate-1 + layer-2 -> h2 (fp16) ----------------
// warp per node; 32-edge batches, prefetched indices, 8-deep predicated row loads.
__global__ void __launch_bounds__(256) k_agg1(const float* __restrict__ W2,
                                              const float* __restrict__ b1) {
    int t = threadIdx.x;
    int lane = t & 31;
    int n = blockIdx.x * 8 + (t >> 5);   // exact: 12500*8 = 100000

    int c0 = lane * 2;
    float4 wa0 = __ldg((const float4*)(W2 + c0 * 8));
    float4 wa1 = __ldg((const float4*)(W2 + c0 * 8 + 4));
    float4 wb0 = __ldg((const float4*)(W2 + c0 * 8 + 8));
    float4 wb1 = __ldg((const float4*)(W2 + c0 * 8 + 12));
    float bb0 = __ldg(b1 + c0);
    float bb1 = __ldg(b1 + c0 + 1);

    int start = g_start[n];
    int deg   = g_indeg[n];

    float a0 = 0.f, a1 = 0.f;
    int sidx = __ldg(&g_csr_src[start + lane]);          // batch 0 (pad-safe)
    for (int i = 0; i < deg; i += 32) {
        int nsidx = __ldg(&g_csr_src[start + i + 32 + lane]);   // prefetch (pad-safe)
        int rem = deg - i;
        #pragma unroll
        for (int jb = 0; jb < 4; jb++) {
            float2 v[8];
            #pragma unroll
            for (int j = 0; j < 8; j++) {
                int e = jb * 8 + j;
                int s = __shfl_sync(~0u, sidx, e);
                v[j] = make_float2(0.f, 0.f);
                if (e < rem)
                    v[j] = __half22float2(__ldg(g_hproj + (size_t)s * 32 + lane));
            }
            #pragma unroll
            for (int j = 0; j < 8; j++) { a0 += v[j].x; a1 += v[j].y; }
            if (jb * 8 + 8 >= rem) break;
        }
        sidx = nsidx;
    }

    float inr = g_innorm[n], onr = g_onorm[n];
    float h0 = fmaxf(fmaf(a0, inr, bb0), 0.f) * onr;
    float h1 = fmaxf(fmaf(a1, inr, bb1), 0.f) * onr;

    float p0 = h0 * wa0.x + h1 * wb0.x;
    float p1 = h0 * wa0.y + h1 * wb0.y;
    float p2 = h0 * wa0.z + h1 * wb0.z;
    float p3 = h0 * wa0.w + h1 * wb0.w;
    float p4 = h0 * wa1.x + h1 * wb1.x;
    float p5 = h0 * wa1.y + h1 * wb1.y;
    float p6 = h0 * wa1.z + h1 * wb1.z;
    float p7 = h0 * wa1.w + h1 * wb1.w;

    #pragma unroll
    for (int off = 16; off > 0; off >>= 1) {
        p0 += __shfl_xor_sync(~0u, p0, off);
        p1 += __shfl_xor_sync(~0u, p1, off);
        p2 += __shfl_xor_sync(~0u, p2, off);
        p3 += __shfl_xor_sync(~0u, p3, off);
        p4 += __shfl_xor_sync(~0u, p4, off);
        p5 += __shfl_xor_sync(~0u, p5, off);
        p6 += __shfl_xor_sync(~0u, p6, off);
        p7 += __shfl_xor_sync(~0u, p7, off);
    }
    if (lane == 0) {
        __half2 hh[4];
        hh[0] = __floats2half2_rn(p0, p1);
        hh[1] = __floats2half2_rn(p2, p3);
        hh[2] = __floats2half2_rn(p4, p5);
        hh[3] = __floats2half2_rn(p6, p7);
        *(uint4*)(g_h2 + (size_t)n * 4) = *(uint4*)hh;
    }
}

// ---------------- launch 7: fused aggregate-2 + softmax ----------------
__global__ void __launch_bounds__(256) k_agg2(const float* __restrict__ b2,
                                              float* __restrict__ out) {
    int t = threadIdx.x;
    int lane = t & 31;
    int n = blockIdx.x * 8 + (t >> 5);   // exact
    int g = lane >> 2, j = lane & 3;

    int start = g_start[n];
    int deg   = g_indeg[n];

    float ax = 0.f, ay = 0.f;
    for (int i = g; i < deg; i += 16) {
        int s0 = __ldg(&g_csr_src[start + i]);                 // pad-safe
        int s1 = __ldg(&g_csr_src[start + i + 8]);
        float2 v0 = __half22float2(__ldg(g_h2 + (size_t)s0 * 4 + j));
        float2 v1 = make_float2(0.f, 0.f);
        if (i + 8 < deg)
            v1 = __half22float2(__ldg(g_h2 + (size_t)s1 * 4 + j));
        ax += v0.x + v1.x; ay += v0.y + v1.y;
    }
    #pragma unroll
    for (int off = 4; off < 32; off <<= 1) {
        ax += __shfl_xor_sync(~0u, ax, off);
        ay += __shfl_xor_sync(~0u, ay, off);
    }

    float inr = g_innorm[n];
    float2 bb = __ldg((const float2*)b2 + j);
    float v0 = fmaf(ax, inr, bb.x);
    float v1 = fmaf(ay, inr, bb.y);
    float m = fmaxf(v0, v1);
    m = fmaxf(m, __shfl_xor_sync(~0u, m, 1));
    m = fmaxf(m, __shfl_xor_sync(~0u, m, 2));
    float e0 = __expf(v0 - m), e1 = __expf(v1 - m);
    float s = e0 + e1;
    s += __shfl_xor_sync(~0u, s, 1);
    s += __shfl_xor_sync(~0u, s, 2);
    float rs = 1.0f / s;
    if (g == 0)
        *(float2*)(out + (size_t)n * NCLS + j * 2) = make_float2(e0 * rs, e1 * rs);
}

extern "C" void kernel_launch(void* const* d_in, const int* in_sizes, int n_in,
                              void* d_out, int out_size) {
    const float* x   = (const float*)d_in[0];
    const int*   src = (const int*)  d_in[1];
    const int*   dst = (const int*)  d_in[2];
    const float* W1  = (const float*)d_in[3];
    const float* b1  = (const float*)d_in[4];
    const float* W2  = (const float*)d_in[5];
    const float* b2  = (const float*)d_in[6];
    float* out = (float*)d_out;

    k_zero<<<NBLK, 256>>>();
    k_degree<<<NED / 256, 256>>>(src, dst);
    k_norm_start<<<NBLK, 256>>>();
    k_gemm1<<<(NND + 127) / 128, 256>>>(x, W1);   // launch #4 -> profiled
    k_fill<<<NED / 256, 256>>>(src, dst);
    k_agg1<<<NND / 8, 256>>>(W2, b1);
    k_agg2<<<NND / 8, 256>>>(b2, out);
}

// round 9
// speedup vs baseline: 1.0193x; 1.0193x over previous
#include <cuda_runtime.h>
#include <cuda_fp16.h>
#include <cstdint>

#define NND 100000
#define NED 3200000
#define IN_DIM 128
#define HID 64
#define NCLS 8
#define NBLK 391        // ceil(NND/256)
#define GEMM_BLKS 782   // ceil(NND/128)
#define DEG_BLKS 12500  // NED/256
#define FILL_BLKS 12500
#define SCALE_BLKS 3125 // NND*8/256

// ---------------- device scratch ----------------
__device__ uint4 g_hproj_raw[(size_t)NND * 8];   // N x 64 halves = 12.8 MB
#define G_HPROJ ((__half2*)g_hproj_raw)
__device__ uint4 g_h2_raw[NND];                  // N x 8 halves = 1.6 MB
#define G_H2 ((__half2*)g_h2_raw)
__device__ float g_onorm[NND];
__device__ float g_innorm[NND];
__device__ int   g_outdeg[NND];
__device__ int   g_indeg[NND];
__device__ int   g_csr_src[NED + 64];
__device__ int   g_start[NND];
__device__ int   g_cursor[NND];
__device__ int   g_total;

// ---------------- mma helpers ----------------
__device__ __forceinline__ uint32_t smem_u32(const void* p) {
    return (uint32_t)__cvta_generic_to_shared(p);
}
__device__ __forceinline__ void ldsm_x4(uint32_t addr, uint32_t& r0, uint32_t& r1,
                                        uint32_t& r2, uint32_t& r3) {
    asm volatile("ldmatrix.sync.aligned.m8n8.x4.shared.b16 {%0,%1,%2,%3}, [%4];"
                 : "=r"(r0), "=r"(r1), "=r"(r2), "=r"(r3) : "r"(addr));
}
__device__ __forceinline__ void ldsm_x4_t(uint32_t addr, uint32_t& r0, uint32_t& r1,
                                          uint32_t& r2, uint32_t& r3) {
    asm volatile("ldmatrix.sync.aligned.m8n8.x4.trans.shared.b16 {%0,%1,%2,%3}, [%4];"
                 : "=r"(r0), "=r"(r1), "=r"(r2), "=r"(r3) : "r"(addr));
}
__device__ __forceinline__ void mma_16816(float (&c)[4], uint32_t a0, uint32_t a1,
                                          uint32_t a2, uint32_t a3,
                                          uint32_t b0, uint32_t b1) {
    asm volatile("mma.sync.aligned.m16n8k16.row.col.f32.f16.f16.f32 "
                 "{%0,%1,%2,%3}, {%4,%5,%6,%7}, {%8,%9}, {%0,%1,%2,%3};"
                 : "+f"(c[0]), "+f"(c[1]), "+f"(c[2]), "+f"(c[3])
                 : "r"(a0), "r"(a1), "r"(a2), "r"(a3), "r"(b0), "r"(b1));
}

// ---------------- launch 1: zero ----------------
__global__ void k_zero() {
    int i = blockIdx.x * 256 + threadIdx.x;
    if (i < NND) { g_outdeg[i] = 0; g_indeg[i] = 0; }
    if (i < 64)  g_csr_src[NED + i] = 0;
    if (i == 0)  g_total = 0;
}

// ---------------- launch 2 (fused A): raw GEMM1 + degree counting ----------------
#define XS_STR 72
#define WS_STR 72

__global__ void __launch_bounds__(256) k_fused_A(const float* __restrict__ x,
                                                 const float* __restrict__ W1,
                                                 const int* __restrict__ src,
                                                 const int* __restrict__ dst) {
    if (blockIdx.x >= GEMM_BLKS) {
        // ---- degree branch: pure fire-and-forget reductions ----
        int e = (blockIdx.x - GEMM_BLKS) * 256 + threadIdx.x;  // exact
        atomicAdd(&g_outdeg[__ldg(src + e)], 1);
        atomicAdd(&g_indeg[__ldg(dst + e)], 1);
        return;
    }

    // ---- gemm branch: hproj_raw = x @ W1 (no norm) ----
    __shared__ __half xs[128 * XS_STR];
    __shared__ __half ws[64 * WS_STR];

    int t = threadIdx.x;
    int w = t >> 5, lane = t & 31;
    int nb = blockIdx.x * 128;

    float acc[8][4] = {};

    uint32_t xbase = smem_u32(xs);
    uint32_t wbase = smem_u32(ws);
    int arow  = (w << 4) + (lane & 15);
    int ahalf = lane >> 4;
    int brow  = lane & 15;
    int bsel  = lane >> 4;

    for (int kc = 0; kc < 2; kc++) {
        #pragma unroll
        for (int i = 0; i < 8; i++) {
            int li  = i * 256 + t;
            int row = li >> 4;
            int f4  = li & 15;
            int gn  = nb + row;
            float4 v = (gn < NND)
                ? __ldg((const float4*)(x + (size_t)gn * IN_DIM + kc * 64) + f4)
                : make_float4(0.f, 0.f, 0.f, 0.f);
            __half2 h[2];
            h[0] = __floats2half2_rn(v.x, v.y);
            h[1] = __floats2half2_rn(v.z, v.w);
            *(uint2*)(xs + row * XS_STR + f4 * 4) = *(uint2*)h;
        }
        #pragma unroll
        for (int i = 0; i < 4; i++) {
            int li = i * 256 + t;
            int kr = li >> 4;
            int f4 = li & 15;
            float4 v = __ldg((const float4*)(W1 + (size_t)(kc * 64 + kr) * HID) + f4);
            __half2 h[2];
            h[0] = __floats2half2_rn(v.x, v.y);
            h[1] = __floats2half2_rn(v.z, v.w);
            *(uint2*)(ws + kr * WS_STR + f4 * 4) = *(uint2*)h;
        }
        __syncthreads();

        #pragma unroll
        for (int ks = 0; ks < 4; ks++) {
            uint32_t a0, a1, a2, a3;
            ldsm_x4(xbase + (uint32_t)(arow * (XS_STR * 2) + ks * 32 + ahalf * 16),
                    a0, a1, a2, a3);
            #pragma unroll
            for (int np = 0; np < 4; np++) {
                uint32_t b0, b1, b2, b3;
                uint32_t baddr = wbase
                    + (uint32_t)((ks * 16 + brow) * (WS_STR * 2))
                    + (uint32_t)((np * 2 + bsel) * 16);
                ldsm_x4_t(baddr, b0, b1, b2, b3);
                mma_16816(acc[2 * np],     a0, a1, a2, a3, b0, b1);
                mma_16816(acc[2 * np + 1], a0, a1, a2, a3, b2, b3);
            }
        }
        __syncthreads();
    }

    int g  = lane >> 2, tg = lane & 3;
    int m0 = nb + (w << 4) + g;
    int m1 = m0 + 8;
    #pragma unroll
    for (int nt = 0; nt < 8; nt++) {
        if (m0 < NND)
            G_HPROJ[(size_t)m0 * 32 + nt * 4 + tg] = __floats2half2_rn(acc[nt][0], acc[nt][1]);
        if (m1 < NND)
            G_HPROJ[(size_t)m1 * 32 + nt * 4 + tg] = __floats2half2_rn(acc[nt][2], acc[nt][3]);
    }
}

// ---------------- launch 3: norms + CSR start offsets ----------------
__global__ void __launch_bounds__(256) k_norm_start() {
    int t = threadIdx.x;
    int n = blockIdx.x * 256 + t;
    int lane = t & 31, w = t >> 5;

    int deg = 0, od = 0;
    if (n < NND) { deg = g_indeg[n]; od = g_outdeg[n]; }

    int scan = deg;
    #pragma unroll
    for (int off = 1; off < 32; off <<= 1) {
        int u = __shfl_up_sync(~0u, scan, off);
        if (lane >= off) scan += u;
    }
    __shared__ int wsum[8];
    __shared__ int sbase;
    if (lane == 31) wsum[w] = scan;
    __syncthreads();
    if (t == 0) {
        int tot = 0;
        #pragma unroll
        for (int i = 0; i < 8; i++) { int v = wsum[i]; wsum[i] = tot; tot += v; }
        sbase = atomicAdd(&g_total, tot);
    }
    __syncthreads();

    if (n < NND) {
        g_onorm[n]  = rsqrtf((float)(od  > 1 ? od  : 1));
        g_innorm[n] = rsqrtf((float)(deg > 1 ? deg : 1));
        int start = sbase + wsum[w] + scan - deg;
        g_start[n]  = start;
        g_cursor[n] = start;
    }
}

// ---------------- launch 4 (PROFILED, fused B): CSR fill + hproj norm-scale ----
__global__ void __launch_bounds__(256) k_fused_B(const int* __restrict__ src,
                                                 const int* __restrict__ dst) {
    if (blockIdx.x < FILL_BLKS) {
        int e = blockIdx.x * 256 + threadIdx.x;   // exact
        int d = __ldg(dst + e);
        int s = __ldg(src + e);
        int pos = atomicAdd(&g_cursor[d], 1);
        g_csr_src[pos] = s;
        return;
    }
    // ---- scale branch: hproj[n] *= onorm[n] (fp32 math) ----
    int idx = (blockIdx.x - FILL_BLKS) * 256 + threadIdx.x;  // exact: 800000 uint4
    int node = idx >> 3;
    uint4 v = g_hproj_raw[idx];
    float nrm = g_onorm[node];
    __half2* h = (__half2*)&v;
    #pragma unroll
    for (int p = 0; p < 4; p++) {
        float2 f = __half22float2(h[p]);
        h[p] = __floats2half2_rn(f.x * nrm, f.y * nrm);
    }
    g_hproj_raw[idx] = v;
}

// ---------------- launch 5: fused aggregate-1 + layer-2 -> h2 (fp16) ----------------
__global__ void __launch_bounds__(256) k_agg1(const float* __restrict__ W2,
                                              const float* __restrict__ b1) {
    int t = threadIdx.x;
    int lane = t & 31;
    int n = blockIdx.x * 8 + (t >> 5);   // exact: 12500*8 = 100000

    int c0 = lane * 2;
    float4 wa0 = __ldg((const float4*)(W2 + c0 * 8));
    float4 wa1 = __ldg((const float4*)(W2 + c0 * 8 + 4));
    float4 wb0 = __ldg((const float4*)(W2 + c0 * 8 + 8));
    float4 wb1 = __ldg((const float4*)(W2 + c0 * 8 + 12));
    float bb0 = __ldg(b1 + c0);
    float bb1 = __ldg(b1 + c0 + 1);

    int start = g_start[n];
    int deg   = g_indeg[n];

    float a0 = 0.f, a1 = 0.f;
    int i = 0;
    while (i < deg) {
        int cnt = min(32, deg - i);
        int sidx = (lane < cnt) ? __ldg(&g_csr_src[start + i + lane]) : 0;
        int j = 0;
        for (; j + 4 <= cnt; j += 4) {
            int s0 = __shfl_sync(~0u, sidx, j);
            int s1 = __shfl_sync(~0u, sidx, j + 1);
            int s2 = __shfl_sync(~0u, sidx, j + 2);
            int s3 = __shfl_sync(~0u, sidx, j + 3);
            float2 v0 = __half22float2(__ldg(G_HPROJ + (size_t)s0 * 32 + lane));
            float2 v1 = __half22float2(__ldg(G_HPROJ + (size_t)s1 * 32 + lane));
            float2 v2 = __half22float2(__ldg(G_HPROJ + (size_t)s2 * 32 + lane));
            float2 v3 = __half22float2(__ldg(G_HPROJ + (size_t)s3 * 32 + lane));
            a0 += v0.x + v1.x; a1 += v0.y + v1.y;
            a0 += v2.x + v3.x; a1 += v2.y + v3.y;
        }
        for (; j < cnt; j++) {
            int s = __shfl_sync(~0u, sidx, j);
            float2 v = __half22float2(__ldg(G_HPROJ + (size_t)s * 32 + lane));
            a0 += v.x; a1 += v.y;
        }
        i += cnt;
    }

    float inr = g_innorm[n], onr = g_onorm[n];
    float h0 = fmaxf(fmaf(a0, inr, bb0), 0.f) * onr;
    float h1 = fmaxf(fmaf(a1, inr, bb1), 0.f) * onr;

    float p0 = h0 * wa0.x + h1 * wb0.x;
    float p1 = h0 * wa0.y + h1 * wb0.y;
    float p2 = h0 * wa0.z + h1 * wb0.z;
    float p3 = h0 * wa0.w + h1 * wb0.w;
    float p4 = h0 * wa1.x + h1 * wb1.x;
    float p5 = h0 * wa1.y + h1 * wb1.y;
    float p6 = h0 * wa1.z + h1 * wb1.z;
    float p7 = h0 * wa1.w + h1 * wb1.w;

    #pragma unroll
    for (int off = 16; off > 0; off >>= 1) {
        p0 += __shfl_xor_sync(~0u, p0, off);
        p1 += __shfl_xor_sync(~0u, p1, off);
        p2 += __shfl_xor_sync(~0u, p2, off);
        p3 += __shfl_xor_sync(~0u, p3, off);
        p4 += __shfl_xor_sync(~0u, p4, off);
        p5 += __shfl_xor_sync(~0u, p5, off);
        p6 += __shfl_xor_sync(~0u, p6, off);
        p7 += __shfl_xor_sync(~0u, p7, off);
    }
    if (lane == 0) {
        __half2 hh[4];
        hh[0] = __floats2half2_rn(p0, p1);
        hh[1] = __floats2half2_rn(p2, p3);
        hh[2] = __floats2half2_rn(p4, p5);
        hh[3] = __floats2half2_rn(p6, p7);
        g_h2_raw[n] = *(uint4*)hh;
    }
}

// ---------------- launch 6: fused aggregate-2 + softmax ----------------
__global__ void __launch_bounds__(256) k_agg2(const float* __restrict__ b2,
                                              float* __restrict__ out) {
    int t = threadIdx.x;
    int lane = t & 31;
    int n = blockIdx.x * 8 + (t >> 5);   // exact
    int g = lane >> 2, j = lane & 3;

    int start = g_start[n];
    int deg   = g_indeg[n];

    float ax = 0.f, ay = 0.f;
    for (int i = g; i < deg; i += 8) {
        int s = __ldg(&g_csr_src[start + i]);
        float2 v = __half22float2(__ldg(G_H2 + (size_t)s * 4 + j));
        ax += v.x; ay += v.y;
    }
    #pragma unroll
    for (int off = 4; off < 32; off <<= 1) {
        ax += __shfl_xor_sync(~0u, ax, off);
        ay += __shfl_xor_sync(~0u, ay, off);
    }

    float inr = g_innorm[n];
    float2 bb = __ldg((const float2*)b2 + j);
    float v0 = fmaf(ax, inr, bb.x);
    float v1 = fmaf(ay, inr, bb.y);
    float m = fmaxf(v0, v1);
    m = fmaxf(m, __shfl_xor_sync(~0u, m, 1));
    m = fmaxf(m, __shfl_xor_sync(~0u, m, 2));
    float e0 = __expf(v0 - m), e1 = __expf(v1 - m);
    float s = e0 + e1;
    s += __shfl_xor_sync(~0u, s, 1);
    s += __shfl_xor_sync(~0u, s, 2);
    float rs = 1.0f / s;
    if (g == 0)
        *(float2*)(out + (size_t)n * NCLS + j * 2) = make_float2(e0 * rs, e1 * rs);
}

extern "C" void kernel_launch(void* const* d_in, const int* in_sizes, int n_in,
                              void* d_out, int out_size) {
    const float* x   = (const float*)d_in[0];
    const int*   src = (const int*)  d_in[1];
    const int*   dst = (const int*)  d_in[2];
    const float* W1  = (const float*)d_in[3];
    const float* b1  = (const float*)d_in[4];
    const float* W2  = (const float*)d_in[5];
    const float* b2  = (const float*)d_in[6];
    float* out = (float*)d_out;

    k_zero<<<NBLK, 256>>>();
    k_fused_A<<<GEMM_BLKS + DEG_BLKS, 256>>>(x, W1, src, dst);
    k_norm_start<<<NBLK, 256>>>();
    k_fused_B<<<FILL_BLKS + SCALE_BLKS, 256>>>(src, dst);   // launch #4 -> profiled
    k_agg1<<<NND / 8, 256>>>(W2, b1);
    k_agg2<<<NND / 8, 256>>>(b2, out);
}